// round 13
// baseline (speedup 1.0000x reference)
#include <cuda_runtime.h>
#include <cuda_fp16.h>
#include <cstdint>

// ============================================================================
// out[b,c] = sum_d W[c,d] * (softmax(mod[b,:])[d] + 1) * x[b,d]
// B=8192, D=1024, C=4096, fp32.
// R9: fp16-accumulate HMMA per K=64 chunk + fp32 master merge per ktile.
// CTA 128x128x64, 128 thr, 4 warps (64x64), 3-stage cp.async, 2 CTAs/SM.
// ============================================================================

#define Bq 8192
#define Dq 1024
#define Cq 4096

#define BM 128
#define BN 128
#define BK 64
#define NT (Dq / BK)        // 16 k-tiles
#define STAGES 3
#define LDH 72              // BK + 8 pad halfs: 144B row stride, conflict-free

#define A_TILE_HALFS (BM * LDH)             // 9216
#define B_TILE_HALFS (BN * LDH)             // 9216
#define STAGE_BYTES ((A_TILE_HALFS + B_TILE_HALFS) * 2)   // 36864
#define SMEM_BYTES (STAGES * STAGE_BYTES)   // 110592 -> 2 CTAs/SM

#define W_CTAS 1024

__device__ __half g_y[(size_t)Bq * Dq];
__device__ __half g_w[(size_t)Cq * Dq];

__device__ __forceinline__ uint32_t smem_u32(const void* p) {
    uint32_t a;
    asm("{ .reg .u64 t; cvta.to.shared.u64 t, %1; cvt.u32.u64 %0, t; }" : "=r"(a) : "l"(p));
    return a;
}

__device__ __forceinline__ void cp_async16(uint32_t dst, const void* src) {
    asm volatile("cp.async.cg.shared.global [%0], [%1], 16;" :: "r"(dst), "l"(src) : "memory");
}
#define CP_COMMIT() asm volatile("cp.async.commit_group;" ::: "memory")
#define CP_WAIT(n)  asm volatile("cp.async.wait_group %0;" :: "n"(n) : "memory")

#define LDM_X4(r0, r1, r2, r3, addr) \
    asm volatile("ldmatrix.sync.aligned.m8n8.x4.shared.b16 {%0,%1,%2,%3}, [%4];" \
                 : "=r"(r0), "=r"(r1), "=r"(r2), "=r"(r3) : "r"(addr))

// fp16-accumulate HMMA: D(f16x2 pair) = A*B + C(f16x2 pair)
__device__ __forceinline__ void mma_fp16_h(uint32_t c[2], uint32_t a0, uint32_t a1,
                                           uint32_t a2, uint32_t a3,
                                           uint32_t b0, uint32_t b1) {
    asm volatile(
        "mma.sync.aligned.m16n8k16.row.col.f16.f16.f16.f16 "
        "{%0,%1}, {%2,%3,%4,%5}, {%6,%7}, {%0,%1};"
        : "+r"(c[0]), "+r"(c[1])
        : "r"(a0), "r"(a1), "r"(a2), "r"(a3), "r"(b0), "r"(b1));
}

// ---------------------------------------------------------------------------
// Fused prologue: CTAs [0, Bq) softmax rows; CTAs [Bq, Bq+W_CTAS) cvt W.
// ---------------------------------------------------------------------------
__global__ __launch_bounds__(256) void prologue_kernel(
    const float* __restrict__ x, const float* __restrict__ mod,
    const float* __restrict__ W,
    __half* __restrict__ y, __half* __restrict__ w16)
{
    const int t = threadIdx.x;
    if (blockIdx.x >= Bq) {
        size_t base = (size_t)(blockIdx.x - Bq) * (256 * 4) + t;
        const float4* src = reinterpret_cast<const float4*>(W);
        uint2* dst = reinterpret_cast<uint2*>(w16);
        float4 v0 = src[base];
        float4 v1 = src[base + 256];
        float4 v2 = src[base + 512];
        float4 v3 = src[base + 768];
        #pragma unroll
        for (int i = 0; i < 4; i++) {
            float4 v = (i == 0) ? v0 : (i == 1) ? v1 : (i == 2) ? v2 : v3;
            __half2 h0 = __floats2half2_rn(v.x, v.y);
            __half2 h1 = __floats2half2_rn(v.z, v.w);
            dst[base + i * 256] = make_uint2(*reinterpret_cast<uint32_t*>(&h0),
                                             *reinterpret_cast<uint32_t*>(&h1));
        }
        return;
    }

    const int b = blockIdx.x;
    const float4 m4 = reinterpret_cast<const float4*>(mod + (size_t)b * Dq)[t];
    const float4 x4 = reinterpret_cast<const float4*>(x + (size_t)b * Dq)[t];

    float mx = fmaxf(fmaxf(m4.x, m4.y), fmaxf(m4.z, m4.w));
    #pragma unroll
    for (int o = 16; o; o >>= 1) mx = fmaxf(mx, __shfl_xor_sync(0xffffffffu, mx, o));

    __shared__ float sred[8];
    int w = t >> 5, l = t & 31;
    if (l == 0) sred[w] = mx;
    __syncthreads();
    float gmx = sred[0];
    #pragma unroll
    for (int i = 1; i < 8; i++) gmx = fmaxf(gmx, sred[i]);
    __syncthreads();

    float e0 = expf(m4.x - gmx), e1 = expf(m4.y - gmx);
    float e2 = expf(m4.z - gmx), e3 = expf(m4.w - gmx);
    float s = e0 + e1 + e2 + e3;
    #pragma unroll
    for (int o = 16; o; o >>= 1) s += __shfl_xor_sync(0xffffffffu, s, o);
    if (l == 0) sred[w] = s;
    __syncthreads();
    float tot = 0.0f;
    #pragma unroll
    for (int i = 0; i < 8; i++) tot += sred[i];
    float inv = 1.0f / tot;

    __half2 h0 = __floats2half2_rn(fmaf(e0, inv, 1.0f) * x4.x,
                                   fmaf(e1, inv, 1.0f) * x4.y);
    __half2 h1 = __floats2half2_rn(fmaf(e2, inv, 1.0f) * x4.z,
                                   fmaf(e3, inv, 1.0f) * x4.w);
    reinterpret_cast<uint2*>(y + (size_t)b * Dq)[t] = make_uint2(
        *reinterpret_cast<uint32_t*>(&h0), *reinterpret_cast<uint32_t*>(&h1));
}

// ---------------------------------------------------------------------------
// GEMM: out = y @ W^T. CTA 128x128x64, 128 threads, 4 warps 2(m) x 2(n),
// warp tile 64x64. fp16-acc HMMA per ktile chunk, fp32 merge. 2 CTAs/SM.
// ---------------------------------------------------------------------------
__global__ __launch_bounds__(128, 2) void gemm_fp16_kernel(
    const __half* __restrict__ A,   // g_y  [B][D]
    const __half* __restrict__ Bw,  // g_w  [C][D]
    float* __restrict__ out)        // [B][C]
{
    extern __shared__ __half smem[];
    const uint32_t sbase = smem_u32(smem);
    const int tid  = threadIdx.x;
    const int wid  = tid >> 5;
    const int lane = tid & 31;
    const int m0 = blockIdx.y * BM;
    const int n0 = blockIdx.x * BN;
    const int warp_m = wid >> 1;   // 0..1
    const int warp_n = wid & 1;    // 0..1

    // --- async tile loader ---
    const int ldrow = tid >> 3;       // 0..15
    const int ldch  = (tid & 7) * 8;  // half-offset of 16B chunk
    auto load_tile = [&](int s, int kt) {
        const int k0 = kt * BK;
        const uint32_t sA = sbase + (uint32_t)(s * STAGE_BYTES);
        const uint32_t sB = sA + A_TILE_HALFS * 2u;
        #pragma unroll
        for (int i = 0; i < 8; i++) {
            int r = ldrow + 16 * i;
            cp_async16(sA + (uint32_t)(r * LDH + ldch) * 2u,
                       A + (size_t)(m0 + r) * Dq + k0 + ldch);
        }
        #pragma unroll
        for (int i = 0; i < 8; i++) {
            int r = ldrow + 16 * i;
            cp_async16(sB + (uint32_t)(r * LDH + ldch) * 2u,
                       Bw + (size_t)(n0 + r) * Dq + k0 + ldch);
        }
    };

    // fp32 master accumulators
    float acc[4][8][4];
    #pragma unroll
    for (int mt = 0; mt < 4; mt++)
        #pragma unroll
        for (int nt = 0; nt < 8; nt++)
            #pragma unroll
            for (int i = 0; i < 4; i++) acc[mt][nt][i] = 0.0f;

    int fetch = 0;
    #pragma unroll
    for (; fetch < STAGES - 1; fetch++) { load_tile(fetch, fetch); CP_COMMIT(); }
    CP_WAIT(STAGES - 2);
    __syncthreads();

    const int lrow = lane & 15;
    const int kh   = (lane >> 4) * 8;
    const uint32_t offA0 = (uint32_t)((warp_m * 64 + lrow) * LDH + kh);
    const uint32_t offB0 = (uint32_t)((warp_n * 64 + lrow) * LDH + kh);

    const int fr = lane >> 2;
    const int fc = lane & 3;

    for (int kt = 0; kt < NT; kt++) {
        const int cur = kt % STAGES;
        if (fetch < NT) { load_tile(fetch % STAGES, fetch); fetch++; CP_COMMIT(); }

        const uint32_t sA = sbase + (uint32_t)(cur * STAGE_BYTES);
        const uint32_t sB = sA + A_TILE_HALFS * 2u;

        // fp16 chunk accumulators for this ktile (K=64 chunk)
        uint32_t hacc[4][8][2];
        #pragma unroll
        for (int mt = 0; mt < 4; mt++)
            #pragma unroll
            for (int nt = 0; nt < 8; nt++) {
                hacc[mt][nt][0] = 0u; hacc[mt][nt][1] = 0u;
            }

        #pragma unroll
        for (int ks = 0; ks < 4; ks++) {
            uint32_t af[4][4];
            uint32_t bf[8][2];
            #pragma unroll
            for (int mt = 0; mt < 4; mt++) {
                uint32_t addr = sA + (offA0 + (uint32_t)(mt * 16 * LDH + ks * 16)) * 2u;
                LDM_X4(af[mt][0], af[mt][1], af[mt][2], af[mt][3], addr);
            }
            #pragma unroll
            for (int np = 0; np < 4; np++) {
                uint32_t addr = sB + (offB0 + (uint32_t)(np * 16 * LDH + ks * 16)) * 2u;
                LDM_X4(bf[2 * np][0], bf[2 * np + 1][0],
                       bf[2 * np][1], bf[2 * np + 1][1], addr);
            }
            #pragma unroll
            for (int mt = 0; mt < 4; mt++)
                #pragma unroll
                for (int nt = 0; nt < 8; nt++)
                    mma_fp16_h(hacc[mt][nt],
                               af[mt][0], af[mt][1], af[mt][2], af[mt][3],
                               bf[nt][0], bf[nt][1]);
        }

        // merge fp16 chunk into fp32 master
        #pragma unroll
        for (int mt = 0; mt < 4; mt++)
            #pragma unroll
            for (int nt = 0; nt < 8; nt++) {
                float2 lo = __half22float2(*reinterpret_cast<__half2*>(&hacc[mt][nt][0]));
                float2 hi = __half22float2(*reinterpret_cast<__half2*>(&hacc[mt][nt][1]));
                acc[mt][nt][0] += lo.x;
                acc[mt][nt][1] += lo.y;
                acc[mt][nt][2] += hi.x;
                acc[mt][nt][3] += hi.y;
            }

        CP_WAIT(STAGES - 2);
        __syncthreads();
    }

    // --- epilogue: float2 stores ---
    #pragma unroll
    for (int mt = 0; mt < 4; mt++) {
        int rg = m0 + warp_m * 64 + mt * 16 + fr;
        #pragma unroll
        for (int nt = 0; nt < 8; nt++) {
            int cg = n0 + warp_n * 64 + nt * 8 + fc * 2;
            float2* p0 = reinterpret_cast<float2*>(out + (size_t)rg * Cq + cg);
            float2* p1 = reinterpret_cast<float2*>(out + (size_t)(rg + 8) * Cq + cg);
            *p0 = make_float2(acc[mt][nt][0], acc[mt][nt][1]);
            *p1 = make_float2(acc[mt][nt][2], acc[mt][nt][3]);
        }
    }
}

// ---------------------------------------------------------------------------
// Host launcher
// ---------------------------------------------------------------------------
extern "C" void kernel_launch(void* const* d_in, const int* in_sizes, int n_in,
                              void* d_out, int out_size)
{
    const float* x   = (const float*)d_in[0];
    const float* mod = (const float*)d_in[1];
    const float* W   = (const float*)d_in[2];
    float* out = (float*)d_out;

    __half* yptr = nullptr;
    __half* wptr = nullptr;
    cudaGetSymbolAddress((void**)&yptr, g_y);
    cudaGetSymbolAddress((void**)&wptr, g_w);

    prologue_kernel<<<Bq + W_CTAS, 256>>>(x, mod, W, yptr, wptr);

    cudaFuncSetAttribute(gemm_fp16_kernel,
                         cudaFuncAttributeMaxDynamicSharedMemorySize, SMEM_BYTES);
    dim3 grid(Cq / BN, Bq / BM);   // (32, 64) = 2048 CTAs
    gemm_fp16_kernel<<<grid, 128, SMEM_BYTES>>>(yptr, wptr, out);
}

// round 14
// speedup vs baseline: 1.3638x; 1.3638x over previous
#include <cuda_runtime.h>
#include <cuda_fp16.h>
#include <cstdint>

// ============================================================================
// out[b,c] = sum_d W[c,d] * (softmax(mod[b,:])[d] + 1) * x[b,d]
// B=8192, D=1024, C=4096, fp32.
// R10: GEMM = R8 exact (fp32-acc m16n8k16, CTA 128x128x64, 4 warps 64x64,
// frag double-buffer, 3-stage cp.async, 2 CTAs/SM). Prologue rebuilt for MLP=4.
// ============================================================================

#define Bq 8192
#define Dq 1024
#define Cq 4096

#define BM 128
#define BN 128
#define BK 64
#define NT (Dq / BK)        // 16 k-tiles
#define STAGES 3
#define LDH 72              // BK + 8 pad halfs: 144B row stride, conflict-free

#define A_TILE_HALFS (BM * LDH)             // 9216
#define B_TILE_HALFS (BN * LDH)             // 9216
#define STAGE_BYTES ((A_TILE_HALFS + B_TILE_HALFS) * 2)   // 36864
#define SMEM_BYTES (STAGES * STAGE_BYTES)   // 110592 -> 2 CTAs/SM

#define W_CTAS 2048         // 4M floats / (128 thr * 16 floats)

__device__ __half g_y[(size_t)Bq * Dq];
__device__ __half g_w[(size_t)Cq * Dq];

__device__ __forceinline__ uint32_t smem_u32(const void* p) {
    uint32_t a;
    asm("{ .reg .u64 t; cvta.to.shared.u64 t, %1; cvt.u32.u64 %0, t; }" : "=r"(a) : "l"(p));
    return a;
}

__device__ __forceinline__ void cp_async16(uint32_t dst, const void* src) {
    asm volatile("cp.async.cg.shared.global [%0], [%1], 16;" :: "r"(dst), "l"(src) : "memory");
}
#define CP_COMMIT() asm volatile("cp.async.commit_group;" ::: "memory")
#define CP_WAIT(n)  asm volatile("cp.async.wait_group %0;" :: "n"(n) : "memory")

#define LDM_X4(r0, r1, r2, r3, addr) \
    asm volatile("ldmatrix.sync.aligned.m8n8.x4.shared.b16 {%0,%1,%2,%3}, [%4];" \
                 : "=r"(r0), "=r"(r1), "=r"(r2), "=r"(r3) : "r"(addr))

__device__ __forceinline__ void mma_fp16(float c[4], uint32_t a0, uint32_t a1,
                                         uint32_t a2, uint32_t a3,
                                         uint32_t b0, uint32_t b1) {
    asm volatile(
        "mma.sync.aligned.m16n8k16.row.col.f32.f16.f16.f32 "
        "{%0,%1,%2,%3}, {%4,%5,%6,%7}, {%8,%9}, {%0,%1,%2,%3};"
        : "+f"(c[0]), "+f"(c[1]), "+f"(c[2]), "+f"(c[3])
        : "r"(a0), "r"(a1), "r"(a2), "r"(a3), "r"(b0), "r"(b1));
}

// ---------------------------------------------------------------------------
// Prologue, 128-thread CTAs, MLP=4.
//   CTAs [0, Bq): softmax row b; each thread covers 2 float4 of mod and x.
//   CTAs [Bq, Bq+W_CTAS): W -> fp16, 16 floats per thread.
// ---------------------------------------------------------------------------
__global__ __launch_bounds__(128) void prologue_kernel(
    const float* __restrict__ x, const float* __restrict__ mod,
    const float* __restrict__ W,
    __half* __restrict__ y, __half* __restrict__ w16)
{
    const int t = threadIdx.x;
    if (blockIdx.x >= Bq) {
        // ---- W -> fp16: 4 x float4 in flight per thread ----
        size_t base = (size_t)(blockIdx.x - Bq) * (128 * 4) + t;
        const float4* src = reinterpret_cast<const float4*>(W);
        uint2* dst = reinterpret_cast<uint2*>(w16);
        float4 v0 = src[base];
        float4 v1 = src[base + 128];
        float4 v2 = src[base + 256];
        float4 v3 = src[base + 384];
        #pragma unroll
        for (int i = 0; i < 4; i++) {
            float4 v = (i == 0) ? v0 : (i == 1) ? v1 : (i == 2) ? v2 : v3;
            __half2 h0 = __floats2half2_rn(v.x, v.y);
            __half2 h1 = __floats2half2_rn(v.z, v.w);
            dst[base + i * 128] = make_uint2(*reinterpret_cast<uint32_t*>(&h0),
                                             *reinterpret_cast<uint32_t*>(&h1));
        }
        return;
    }

    // ---- softmax row: 128 threads, 2 float4 per operand (MLP=4) ----
    const int b = blockIdx.x;
    const float4* mrow = reinterpret_cast<const float4*>(mod + (size_t)b * Dq);
    const float4* xrow = reinterpret_cast<const float4*>(x + (size_t)b * Dq);
    const float4 ma = mrow[t];
    const float4 mb = mrow[t + 128];
    const float4 xa = xrow[t];
    const float4 xb = xrow[t + 128];

    float mx = fmaxf(fmaxf(fmaxf(ma.x, ma.y), fmaxf(ma.z, ma.w)),
                     fmaxf(fmaxf(mb.x, mb.y), fmaxf(mb.z, mb.w)));
    #pragma unroll
    for (int o = 16; o; o >>= 1) mx = fmaxf(mx, __shfl_xor_sync(0xffffffffu, mx, o));

    __shared__ float sred[4];
    int w = t >> 5, l = t & 31;
    if (l == 0) sred[w] = mx;
    __syncthreads();
    float gmx = fmaxf(fmaxf(sred[0], sred[1]), fmaxf(sred[2], sred[3]));
    __syncthreads();

    float ea0 = expf(ma.x - gmx), ea1 = expf(ma.y - gmx);
    float ea2 = expf(ma.z - gmx), ea3 = expf(ma.w - gmx);
    float eb0 = expf(mb.x - gmx), eb1 = expf(mb.y - gmx);
    float eb2 = expf(mb.z - gmx), eb3 = expf(mb.w - gmx);
    float s = (ea0 + ea1 + ea2 + ea3) + (eb0 + eb1 + eb2 + eb3);
    #pragma unroll
    for (int o = 16; o; o >>= 1) s += __shfl_xor_sync(0xffffffffu, s, o);
    if (l == 0) sred[w] = s;
    __syncthreads();
    float inv = 1.0f / (sred[0] + sred[1] + sred[2] + sred[3]);

    uint2* yrow = reinterpret_cast<uint2*>(y + (size_t)b * Dq);
    {
        __half2 h0 = __floats2half2_rn(fmaf(ea0, inv, 1.0f) * xa.x,
                                       fmaf(ea1, inv, 1.0f) * xa.y);
        __half2 h1 = __floats2half2_rn(fmaf(ea2, inv, 1.0f) * xa.z,
                                       fmaf(ea3, inv, 1.0f) * xa.w);
        yrow[t] = make_uint2(*reinterpret_cast<uint32_t*>(&h0),
                             *reinterpret_cast<uint32_t*>(&h1));
    }
    {
        __half2 h0 = __floats2half2_rn(fmaf(eb0, inv, 1.0f) * xb.x,
                                       fmaf(eb1, inv, 1.0f) * xb.y);
        __half2 h1 = __floats2half2_rn(fmaf(eb2, inv, 1.0f) * xb.z,
                                       fmaf(eb3, inv, 1.0f) * xb.w);
        yrow[t + 128] = make_uint2(*reinterpret_cast<uint32_t*>(&h0),
                                   *reinterpret_cast<uint32_t*>(&h1));
    }
}

// ---------------------------------------------------------------------------
// GEMM (R8 exact): out = y @ W^T. CTA 128x128x64, 128 threads, 4 warps
// 2(m) x 2(n), warp tile 64x64, ks-level frag double-buffering, 2 CTAs/SM.
// ---------------------------------------------------------------------------
__global__ __launch_bounds__(128, 2) void gemm_fp16_kernel(
    const __half* __restrict__ A,   // g_y  [B][D]
    const __half* __restrict__ Bw,  // g_w  [C][D]
    float* __restrict__ out)        // [B][C]
{
    extern __shared__ __half smem[];
    const uint32_t sbase = smem_u32(smem);
    const int tid  = threadIdx.x;
    const int wid  = tid >> 5;
    const int lane = tid & 31;
    const int m0 = blockIdx.y * BM;
    const int n0 = blockIdx.x * BN;
    const int warp_m = wid >> 1;   // 0..1
    const int warp_n = wid & 1;    // 0..1

    const int ldrow = tid >> 3;       // 0..15
    const int ldch  = (tid & 7) * 8;  // half-offset of 16B chunk
    auto load_tile = [&](int s, int kt) {
        const int k0 = kt * BK;
        const uint32_t sA = sbase + (uint32_t)(s * STAGE_BYTES);
        const uint32_t sB = sA + A_TILE_HALFS * 2u;
        #pragma unroll
        for (int i = 0; i < 8; i++) {
            int r = ldrow + 16 * i;
            cp_async16(sA + (uint32_t)(r * LDH + ldch) * 2u,
                       A + (size_t)(m0 + r) * Dq + k0 + ldch);
        }
        #pragma unroll
        for (int i = 0; i < 8; i++) {
            int r = ldrow + 16 * i;
            cp_async16(sB + (uint32_t)(r * LDH + ldch) * 2u,
                       Bw + (size_t)(n0 + r) * Dq + k0 + ldch);
        }
    };

    float acc[4][8][4];
    #pragma unroll
    for (int mt = 0; mt < 4; mt++)
        #pragma unroll
        for (int nt = 0; nt < 8; nt++)
            #pragma unroll
            for (int i = 0; i < 4; i++) acc[mt][nt][i] = 0.0f;

    int fetch = 0;
    #pragma unroll
    for (; fetch < STAGES - 1; fetch++) { load_tile(fetch, fetch); CP_COMMIT(); }
    CP_WAIT(STAGES - 2);
    __syncthreads();

    const int lrow = lane & 15;
    const int kh   = (lane >> 4) * 8;
    const uint32_t offA0 = (uint32_t)((warp_m * 64 + lrow) * LDH + kh);
    const uint32_t offB0 = (uint32_t)((warp_n * 64 + lrow) * LDH + kh);

    const int fr = lane >> 2;
    const int fc = lane & 3;

    uint32_t af[2][4][4];
    uint32_t bf[2][8][2];

    auto load_frags = [&](int buf, uint32_t sA, uint32_t sB, int ks) {
        #pragma unroll
        for (int mt = 0; mt < 4; mt++) {
            uint32_t addr = sA + (offA0 + (uint32_t)(mt * 16 * LDH + ks * 16)) * 2u;
            LDM_X4(af[buf][mt][0], af[buf][mt][1], af[buf][mt][2], af[buf][mt][3], addr);
        }
        #pragma unroll
        for (int np = 0; np < 4; np++) {
            uint32_t addr = sB + (offB0 + (uint32_t)(np * 16 * LDH + ks * 16)) * 2u;
            LDM_X4(bf[buf][2 * np][0], bf[buf][2 * np + 1][0],
                   bf[buf][2 * np][1], bf[buf][2 * np + 1][1], addr);
        }
    };

    {
        const uint32_t sA0 = sbase;
        const uint32_t sB0 = sA0 + A_TILE_HALFS * 2u;
        load_frags(0, sA0, sB0, 0);
    }

    for (int kt = 0; kt < NT; kt++) {
        const int cur = kt % STAGES;
        if (fetch < NT) { load_tile(fetch % STAGES, fetch); fetch++; CP_COMMIT(); }

        const uint32_t sA = sbase + (uint32_t)(cur * STAGE_BYTES);
        const uint32_t sB = sA + A_TILE_HALFS * 2u;

        #pragma unroll
        for (int ks = 0; ks < 4; ks++) {
            const int buf = ks & 1;
            if (ks < 3) load_frags(buf ^ 1, sA, sB, ks + 1);
            #pragma unroll
            for (int mt = 0; mt < 4; mt++)
                #pragma unroll
                for (int nt = 0; nt < 8; nt++)
                    mma_fp16(acc[mt][nt],
                             af[buf][mt][0], af[buf][mt][1], af[buf][mt][2], af[buf][mt][3],
                             bf[buf][nt][0], bf[buf][nt][1]);
        }

        CP_WAIT(STAGES - 2);
        __syncthreads();
        if (kt + 1 < NT) {
            const uint32_t sAn = sbase + (uint32_t)(((kt + 1) % STAGES) * STAGE_BYTES);
            const uint32_t sBn = sAn + A_TILE_HALFS * 2u;
            load_frags(0, sAn, sBn, 0);
        }
    }

    // --- epilogue: float2 stores ---
    #pragma unroll
    for (int mt = 0; mt < 4; mt++) {
        int rg = m0 + warp_m * 64 + mt * 16 + fr;
        #pragma unroll
        for (int nt = 0; nt < 8; nt++) {
            int cg = n0 + warp_n * 64 + nt * 8 + fc * 2;
            float2* p0 = reinterpret_cast<float2*>(out + (size_t)rg * Cq + cg);
            float2* p1 = reinterpret_cast<float2*>(out + (size_t)(rg + 8) * Cq + cg);
            *p0 = make_float2(acc[mt][nt][0], acc[mt][nt][1]);
            *p1 = make_float2(acc[mt][nt][2], acc[mt][nt][3]);
        }
    }
}

// ---------------------------------------------------------------------------
// Host launcher
// ---------------------------------------------------------------------------
extern "C" void kernel_launch(void* const* d_in, const int* in_sizes, int n_in,
                              void* d_out, int out_size)
{
    const float* x   = (const float*)d_in[0];
    const float* mod = (const float*)d_in[1];
    const float* W   = (const float*)d_in[2];
    float* out = (float*)d_out;

    __half* yptr = nullptr;
    __half* wptr = nullptr;
    cudaGetSymbolAddress((void**)&yptr, g_y);
    cudaGetSymbolAddress((void**)&wptr, g_w);

    prologue_kernel<<<Bq + W_CTAS, 128>>>(x, mod, W, yptr, wptr);

    cudaFuncSetAttribute(gemm_fp16_kernel,
                         cudaFuncAttributeMaxDynamicSharedMemorySize, SMEM_BYTES);
    dim3 grid(Cq / BN, Bq / BM);   // (32, 64) = 2048 CTAs
    gemm_fp16_kernel<<<grid, 128, SMEM_BYTES>>>(yptr, wptr, out);
}

// round 15
// speedup vs baseline: 2.0471x; 1.5011x over previous
#include <cuda_runtime.h>
#include <cuda_fp16.h>
#include <cstdint>

// ============================================================================
// out[b,c] = sum_d W[c,d] * (softmax(mod[b,:])[d] + 1) * x[b,d]
// B=8192, D=1024, C=4096, fp32.
// R11 (= R10 re-bench): GEMM at mma.sync fp32-acc cycle floor
//   (CTA 128x128x64, 4 warps 64x64, frag double-buffer, 3-stage, 2 CTAs/SM);
//   prologue 128-thr MLP=4. R10's +95us was clock/DVFS noise (all pipe %
//   identical, wall x1.57, HBM GB/s /1.57).
// ============================================================================

#define Bq 8192
#define Dq 1024
#define Cq 4096

#define BM 128
#define BN 128
#define BK 64
#define NT (Dq / BK)        // 16 k-tiles
#define STAGES 3
#define LDH 72              // BK + 8 pad halfs: 144B row stride, conflict-free

#define A_TILE_HALFS (BM * LDH)             // 9216
#define B_TILE_HALFS (BN * LDH)             // 9216
#define STAGE_BYTES ((A_TILE_HALFS + B_TILE_HALFS) * 2)   // 36864
#define SMEM_BYTES (STAGES * STAGE_BYTES)   // 110592 -> 2 CTAs/SM

#define W_CTAS 2048         // 4M floats / (128 thr * 16 floats)

__device__ __half g_y[(size_t)Bq * Dq];
__device__ __half g_w[(size_t)Cq * Dq];

__device__ __forceinline__ uint32_t smem_u32(const void* p) {
    uint32_t a;
    asm("{ .reg .u64 t; cvta.to.shared.u64 t, %1; cvt.u32.u64 %0, t; }" : "=r"(a) : "l"(p));
    return a;
}

__device__ __forceinline__ void cp_async16(uint32_t dst, const void* src) {
    asm volatile("cp.async.cg.shared.global [%0], [%1], 16;" :: "r"(dst), "l"(src) : "memory");
}
#define CP_COMMIT() asm volatile("cp.async.commit_group;" ::: "memory")
#define CP_WAIT(n)  asm volatile("cp.async.wait_group %0;" :: "n"(n) : "memory")

#define LDM_X4(r0, r1, r2, r3, addr) \
    asm volatile("ldmatrix.sync.aligned.m8n8.x4.shared.b16 {%0,%1,%2,%3}, [%4];" \
                 : "=r"(r0), "=r"(r1), "=r"(r2), "=r"(r3) : "r"(addr))

__device__ __forceinline__ void mma_fp16(float c[4], uint32_t a0, uint32_t a1,
                                         uint32_t a2, uint32_t a3,
                                         uint32_t b0, uint32_t b1) {
    asm volatile(
        "mma.sync.aligned.m16n8k16.row.col.f32.f16.f16.f32 "
        "{%0,%1,%2,%3}, {%4,%5,%6,%7}, {%8,%9}, {%0,%1,%2,%3};"
        : "+f"(c[0]), "+f"(c[1]), "+f"(c[2]), "+f"(c[3])
        : "r"(a0), "r"(a1), "r"(a2), "r"(a3), "r"(b0), "r"(b1));
}

// ---------------------------------------------------------------------------
// Prologue, 128-thread CTAs, MLP=4.
//   CTAs [0, Bq): softmax row b; 2 float4 of mod and x per thread.
//   CTAs [Bq, Bq+W_CTAS): W -> fp16, 16 floats per thread.
// ---------------------------------------------------------------------------
__global__ __launch_bounds__(128) void prologue_kernel(
    const float* __restrict__ x, const float* __restrict__ mod,
    const float* __restrict__ W,
    __half* __restrict__ y, __half* __restrict__ w16)
{
    const int t = threadIdx.x;
    if (blockIdx.x >= Bq) {
        size_t base = (size_t)(blockIdx.x - Bq) * (128 * 4) + t;
        const float4* src = reinterpret_cast<const float4*>(W);
        uint2* dst = reinterpret_cast<uint2*>(w16);
        float4 v0 = src[base];
        float4 v1 = src[base + 128];
        float4 v2 = src[base + 256];
        float4 v3 = src[base + 384];
        #pragma unroll
        for (int i = 0; i < 4; i++) {
            float4 v = (i == 0) ? v0 : (i == 1) ? v1 : (i == 2) ? v2 : v3;
            __half2 h0 = __floats2half2_rn(v.x, v.y);
            __half2 h1 = __floats2half2_rn(v.z, v.w);
            dst[base + i * 128] = make_uint2(*reinterpret_cast<uint32_t*>(&h0),
                                             *reinterpret_cast<uint32_t*>(&h1));
        }
        return;
    }

    const int b = blockIdx.x;
    const float4* mrow = reinterpret_cast<const float4*>(mod + (size_t)b * Dq);
    const float4* xrow = reinterpret_cast<const float4*>(x + (size_t)b * Dq);
    const float4 ma = mrow[t];
    const float4 mb = mrow[t + 128];
    const float4 xa = xrow[t];
    const float4 xb = xrow[t + 128];

    float mx = fmaxf(fmaxf(fmaxf(ma.x, ma.y), fmaxf(ma.z, ma.w)),
                     fmaxf(fmaxf(mb.x, mb.y), fmaxf(mb.z, mb.w)));
    #pragma unroll
    for (int o = 16; o; o >>= 1) mx = fmaxf(mx, __shfl_xor_sync(0xffffffffu, mx, o));

    __shared__ float sred[4];
    int w = t >> 5, l = t & 31;
    if (l == 0) sred[w] = mx;
    __syncthreads();
    float gmx = fmaxf(fmaxf(sred[0], sred[1]), fmaxf(sred[2], sred[3]));
    __syncthreads();

    float ea0 = expf(ma.x - gmx), ea1 = expf(ma.y - gmx);
    float ea2 = expf(ma.z - gmx), ea3 = expf(ma.w - gmx);
    float eb0 = expf(mb.x - gmx), eb1 = expf(mb.y - gmx);
    float eb2 = expf(mb.z - gmx), eb3 = expf(mb.w - gmx);
    float s = (ea0 + ea1 + ea2 + ea3) + (eb0 + eb1 + eb2 + eb3);
    #pragma unroll
    for (int o = 16; o; o >>= 1) s += __shfl_xor_sync(0xffffffffu, s, o);
    if (l == 0) sred[w] = s;
    __syncthreads();
    float inv = 1.0f / (sred[0] + sred[1] + sred[2] + sred[3]);

    uint2* yrow = reinterpret_cast<uint2*>(y + (size_t)b * Dq);
    {
        __half2 h0 = __floats2half2_rn(fmaf(ea0, inv, 1.0f) * xa.x,
                                       fmaf(ea1, inv, 1.0f) * xa.y);
        __half2 h1 = __floats2half2_rn(fmaf(ea2, inv, 1.0f) * xa.z,
                                       fmaf(ea3, inv, 1.0f) * xa.w);
        yrow[t] = make_uint2(*reinterpret_cast<uint32_t*>(&h0),
                             *reinterpret_cast<uint32_t*>(&h1));
    }
    {
        __half2 h0 = __floats2half2_rn(fmaf(eb0, inv, 1.0f) * xb.x,
                                       fmaf(eb1, inv, 1.0f) * xb.y);
        __half2 h1 = __floats2half2_rn(fmaf(eb2, inv, 1.0f) * xb.z,
                                       fmaf(eb3, inv, 1.0f) * xb.w);
        yrow[t + 128] = make_uint2(*reinterpret_cast<uint32_t*>(&h0),
                                   *reinterpret_cast<uint32_t*>(&h1));
    }
}

// ---------------------------------------------------------------------------
// GEMM: out = y @ W^T. CTA 128x128x64, 128 threads, 4 warps 2(m) x 2(n),
// warp tile 64x64, ks-level frag double-buffering, 2 CTAs/SM.
// ---------------------------------------------------------------------------
__global__ __launch_bounds__(128, 2) void gemm_fp16_kernel(
    const __half* __restrict__ A,   // g_y  [B][D]
    const __half* __restrict__ Bw,  // g_w  [C][D]
    float* __restrict__ out)        // [B][C]
{
    extern __shared__ __half smem[];
    const uint32_t sbase = smem_u32(smem);
    const int tid  = threadIdx.x;
    const int wid  = tid >> 5;
    const int lane = tid & 31;
    const int m0 = blockIdx.y * BM;
    const int n0 = blockIdx.x * BN;
    const int warp_m = wid >> 1;   // 0..1
    const int warp_n = wid & 1;    // 0..1

    const int ldrow = tid >> 3;       // 0..15
    const int ldch  = (tid & 7) * 8;  // half-offset of 16B chunk
    auto load_tile = [&](int s, int kt) {
        const int k0 = kt * BK;
        const uint32_t sA = sbase + (uint32_t)(s * STAGE_BYTES);
        const uint32_t sB = sA + A_TILE_HALFS * 2u;
        #pragma unroll
        for (int i = 0; i < 8; i++) {
            int r = ldrow + 16 * i;
            cp_async16(sA + (uint32_t)(r * LDH + ldch) * 2u,
                       A + (size_t)(m0 + r) * Dq + k0 + ldch);
        }
        #pragma unroll
        for (int i = 0; i < 8; i++) {
            int r = ldrow + 16 * i;
            cp_async16(sB + (uint32_t)(r * LDH + ldch) * 2u,
                       Bw + (size_t)(n0 + r) * Dq + k0 + ldch);
        }
    };

    float acc[4][8][4];
    #pragma unroll
    for (int mt = 0; mt < 4; mt++)
        #pragma unroll
        for (int nt = 0; nt < 8; nt++)
            #pragma unroll
            for (int i = 0; i < 4; i++) acc[mt][nt][i] = 0.0f;

    int fetch = 0;
    #pragma unroll
    for (; fetch < STAGES - 1; fetch++) { load_tile(fetch, fetch); CP_COMMIT(); }
    CP_WAIT(STAGES - 2);
    __syncthreads();

    const int lrow = lane & 15;
    const int kh   = (lane >> 4) * 8;
    const uint32_t offA0 = (uint32_t)((warp_m * 64 + lrow) * LDH + kh);
    const uint32_t offB0 = (uint32_t)((warp_n * 64 + lrow) * LDH + kh);

    const int fr = lane >> 2;
    const int fc = lane & 3;

    uint32_t af[2][4][4];
    uint32_t bf[2][8][2];

    auto load_frags = [&](int buf, uint32_t sA, uint32_t sB, int ks) {
        #pragma unroll
        for (int mt = 0; mt < 4; mt++) {
            uint32_t addr = sA + (offA0 + (uint32_t)(mt * 16 * LDH + ks * 16)) * 2u;
            LDM_X4(af[buf][mt][0], af[buf][mt][1], af[buf][mt][2], af[buf][mt][3], addr);
        }
        #pragma unroll
        for (int np = 0; np < 4; np++) {
            uint32_t addr = sB + (offB0 + (uint32_t)(np * 16 * LDH + ks * 16)) * 2u;
            LDM_X4(bf[buf][2 * np][0], bf[buf][2 * np + 1][0],
                   bf[buf][2 * np][1], bf[buf][2 * np + 1][1], addr);
        }
    };

    {
        const uint32_t sA0 = sbase;
        const uint32_t sB0 = sA0 + A_TILE_HALFS * 2u;
        load_frags(0, sA0, sB0, 0);
    }

    for (int kt = 0; kt < NT; kt++) {
        const int cur = kt % STAGES;
        if (fetch < NT) { load_tile(fetch % STAGES, fetch); fetch++; CP_COMMIT(); }

        const uint32_t sA = sbase + (uint32_t)(cur * STAGE_BYTES);
        const uint32_t sB = sA + A_TILE_HALFS * 2u;

        #pragma unroll
        for (int ks = 0; ks < 4; ks++) {
            const int buf = ks & 1;
            if (ks < 3) load_frags(buf ^ 1, sA, sB, ks + 1);
            #pragma unroll
            for (int mt = 0; mt < 4; mt++)
                #pragma unroll
                for (int nt = 0; nt < 8; nt++)
                    mma_fp16(acc[mt][nt],
                             af[buf][mt][0], af[buf][mt][1], af[buf][mt][2], af[buf][mt][3],
                             bf[buf][nt][0], bf[buf][nt][1]);
        }

        CP_WAIT(STAGES - 2);
        __syncthreads();
        if (kt + 1 < NT) {
            const uint32_t sAn = sbase + (uint32_t)(((kt + 1) % STAGES) * STAGE_BYTES);
            const uint32_t sBn = sAn + A_TILE_HALFS * 2u;
            load_frags(0, sAn, sBn, 0);
        }
    }

    // --- epilogue: float2 stores ---
    #pragma unroll
    for (int mt = 0; mt < 4; mt++) {
        int rg = m0 + warp_m * 64 + mt * 16 + fr;
        #pragma unroll
        for (int nt = 0; nt < 8; nt++) {
            int cg = n0 + warp_n * 64 + nt * 8 + fc * 2;
            float2* p0 = reinterpret_cast<float2*>(out + (size_t)rg * Cq + cg);
            float2* p1 = reinterpret_cast<float2*>(out + (size_t)(rg + 8) * Cq + cg);
            *p0 = make_float2(acc[mt][nt][0], acc[mt][nt][1]);
            *p1 = make_float2(acc[mt][nt][2], acc[mt][nt][3]);
        }
    }
}

// ---------------------------------------------------------------------------
// Host launcher
// ---------------------------------------------------------------------------
extern "C" void kernel_launch(void* const* d_in, const int* in_sizes, int n_in,
                              void* d_out, int out_size)
{
    const float* x   = (const float*)d_in[0];
    const float* mod = (const float*)d_in[1];
    const float* W   = (const float*)d_in[2];
    float* out = (float*)d_out;

    __half* yptr = nullptr;
    __half* wptr = nullptr;
    cudaGetSymbolAddress((void**)&yptr, g_y);
    cudaGetSymbolAddress((void**)&wptr, g_w);

    prologue_kernel<<<Bq + W_CTAS, 128>>>(x, mod, W, yptr, wptr);

    cudaFuncSetAttribute(gemm_fp16_kernel,
                         cudaFuncAttributeMaxDynamicSharedMemorySize, SMEM_BYTES);
    dim3 grid(Cq / BN, Bq / BM);   // (32, 64) = 2048 CTAs
    gemm_fp16_kernel<<<grid, 128, SMEM_BYTES>>>(yptr, wptr, out);
}